// round 14
// baseline (speedup 1.0000x reference)
#include <cuda_runtime.h>
#include <cuda_bf16.h>
#include <cstdint>

#define BB 4
#define SS 2048
#define DD 1024
#define HH 16
#define HDD 64
#define MM (BB*SS)   // 8192

// Scratch (allocation-free rule: __device__ globals)
__device__ float g_q[(size_t)BB*HH*SS*HDD];   // [bh][s][e] 32MB
__device__ float g_k[(size_t)BB*HH*SS*HDD];
__device__ float g_v[(size_t)BB*HH*SS*HDD];
__device__ float g_c[(size_t)MM*DD];          // attn out, concat layout [b,s,D]

__device__ __forceinline__ uint32_t f2tf32(float f) {
    uint32_t u;
    asm("cvt.rna.tf32.f32 %0, %1;" : "=r"(u) : "f"(f));
    return u;
}

__device__ __forceinline__ uint4 cvt4(float4 v) {
    return make_uint4(f2tf32(v.x), f2tf32(v.y), f2tf32(v.z), f2tf32(v.w));
}

__device__ __forceinline__ void split_tf32(float x, uint32_t& hi, uint32_t& lo) {
    hi = f2tf32(x);
    lo = f2tf32(x - __uint_as_float(hi));
}

#define MMA_TF32(c, a, b0, b1) \
    asm volatile("mma.sync.aligned.m16n8k8.row.col.f32.tf32.tf32.f32 " \
        "{%0,%1,%2,%3}, {%4,%5,%6,%7}, {%8,%9}, {%0,%1,%2,%3};" \
        : "+f"((c)[0]), "+f"((c)[1]), "+f"((c)[2]), "+f"((c)[3]) \
        : "r"((a)[0]), "r"((a)[1]), "r"((a)[2]), "r"((a)[3]), "r"(b0), "r"(b1))

// ---------------------------------------------------------------------------
// Kernel 1: QKV projection, tf32 mma.sync, register-staged double buffer.
// CTA 256x64 (one head per n-block), BK=32, 256 thr / 8 warps, warp 64x32.
// ---------------------------------------------------------------------------
#define QAPAD 36
#define QBPAD 72
#define QA_WORDS (256 * QAPAD)          // 9216
#define QSTAGE   (QA_WORDS + 32 * QBPAD)  // 11520 words = 46080 B

__global__ __launch_bounds__(256) void qkv_mma(
    const float* __restrict__ x,  const float* __restrict__ Wq,
    const float* __restrict__ Wk, const float* __restrict__ Wv)
{
    extern __shared__ uint32_t sq[];    // 2 stages

    const int tid = threadIdx.x;
    const int wid = tid >> 5, lane = tid & 31;
    const int m0w = (wid & 3) * 64, n0w = (wid >> 2) * 32;
    const int m0 = blockIdx.x * 256;
    const int ct = blockIdx.y;                 // 0..47: which*16 + h
    const int which = ct >> 4, h = ct & 15;
    const float* W = (which == 0 ? Wq : which == 1 ? Wk : Wv)
                   + (size_t)h * DD * HDD;
    float* ob = (which == 0) ? g_q : (which == 1) ? g_k : g_v;

    const int lr = lane >> 2, lc = lane & 3;

    float acc[4][4][4];
#pragma unroll
    for (int mt = 0; mt < 4; mt++)
#pragma unroll
        for (int nt = 0; nt < 4; nt++)
#pragma unroll
            for (int i = 0; i < 4; i++) acc[mt][nt][i] = 0.f;

    float4 stA[8], stB[2];

    // ---- prologue: load tile 0 and commit to stage 0 ----
#pragma unroll
    for (int i = 0; i < 8; i++) {
        int f4 = tid + i * 256, row = f4 >> 3, c4 = f4 & 7;
        stA[i] = *(const float4*)&x[(size_t)(m0 + row) * DD + c4 * 4];
    }
#pragma unroll
    for (int i = 0; i < 2; i++) {
        int f4 = tid + i * 256, row = f4 >> 4, c4 = f4 & 15;
        stB[i] = *(const float4*)&W[(size_t)row * HDD + c4 * 4];
    }
#pragma unroll
    for (int i = 0; i < 8; i++) {
        int f4 = tid + i * 256, row = f4 >> 3, c4 = f4 & 7;
        *(uint4*)&sq[row * QAPAD + c4 * 4] = cvt4(stA[i]);
    }
#pragma unroll
    for (int i = 0; i < 2; i++) {
        int f4 = tid + i * 256, row = f4 >> 4, c4 = f4 & 15;
        *(uint4*)&sq[QA_WORDS + row * QBPAD + c4 * 4] = cvt4(stB[i]);
    }
    __syncthreads();

    for (int kt = 0; kt < 32; kt++) {
        const int cur = kt & 1;
        uint32_t* As = sq + cur * QSTAGE;
        uint32_t* Bs = As + QA_WORDS;
        const bool more = (kt + 1 < 32);

        // ---- issue loads for next tile (non-blocking) ----
        if (more) {
            const int k1 = (kt + 1) * 32;
#pragma unroll
            for (int i = 0; i < 8; i++) {
                int f4 = tid + i * 256, row = f4 >> 3, c4 = f4 & 7;
                stA[i] = *(const float4*)&x[(size_t)(m0 + row) * DD + k1 + c4 * 4];
            }
#pragma unroll
            for (int i = 0; i < 2; i++) {
                int f4 = tid + i * 256, row = f4 >> 4, c4 = f4 & 15;
                stB[i] = *(const float4*)&W[(size_t)(k1 + row) * HDD + c4 * 4];
            }
        }

        // ---- compute current tile (covers load latency) ----
#pragma unroll
        for (int ks = 0; ks < 4; ks++) {
            const int k8 = ks * 8;
            uint32_t a[4][4];
#pragma unroll
            for (int mt = 0; mt < 4; mt++) {
                const int r = (m0w + mt * 16 + lr) * QAPAD;
                a[mt][0] = As[r + k8 + lc];
                a[mt][1] = As[r + 8 * QAPAD + k8 + lc];
                a[mt][2] = As[r + k8 + lc + 4];
                a[mt][3] = As[r + 8 * QAPAD + k8 + lc + 4];
            }
#pragma unroll
            for (int nt = 0; nt < 4; nt++) {
                const int n = n0w + nt * 8 + lr;
                uint32_t b0 = Bs[(k8 + lc) * QBPAD + n];
                uint32_t b1 = Bs[(k8 + lc + 4) * QBPAD + n];
#pragma unroll
                for (int mt = 0; mt < 4; mt++)
                    MMA_TF32(acc[mt][nt], a[mt], b0, b1);
            }
        }

        // ---- commit next tile to the other stage ----
        if (more) {
            uint32_t* Ad = sq + (cur ^ 1) * QSTAGE;
            uint32_t* Bd = Ad + QA_WORDS;
#pragma unroll
            for (int i = 0; i < 8; i++) {
                int f4 = tid + i * 256, row = f4 >> 3, c4 = f4 & 7;
                *(uint4*)&Ad[row * QAPAD + c4 * 4] = cvt4(stA[i]);
            }
#pragma unroll
            for (int i = 0; i < 2; i++) {
                int f4 = tid + i * 256, row = f4 >> 4, c4 = f4 & 15;
                *(uint4*)&Bd[row * QBPAD + c4 * 4] = cvt4(stB[i]);
            }
        }
        __syncthreads();
    }

    // ---- Epilogue: scatter into [bh][s][e] ----
#pragma unroll
    for (int mt = 0; mt < 4; mt++)
#pragma unroll
    for (int half = 0; half < 2; half++) {
        const int m = m0 + m0w + mt * 16 + lr + half * 8;
        const int b = m >> 11, srow = m & (SS - 1);
        float* dst = ob + ((size_t)(b * HH + h) * SS + srow) * HDD;
#pragma unroll
        for (int nt = 0; nt < 4; nt++) {
            const int e = n0w + nt * 8 + 2 * lc;
            *(float2*)(dst + e) =
                make_float2(acc[mt][nt][half * 2], acc[mt][nt][half * 2 + 1]);
        }
    }
}

// ---------------------------------------------------------------------------
// Kernel 2: flash attention via tf32 mma.sync (byte-identical to R9-R11).
// ---------------------------------------------------------------------------
#define SQ_W 72
#define SK_W 68
#define SV_W 72
#define SP_W 72

#define OFF_QTH 0
#define OFF_QTL 4608
#define OFF_KAH 9216
#define OFF_KAL 13568
#define OFF_VS  17920
#define OFF_PT  22528
#define OFF_CORR 27136
#define OFF_LROW 27200
#define ATTN_SMEM_WORDS 27264   // * 4 = 109056 bytes

__global__ __launch_bounds__(128) void attn_mma() {
    extern __shared__ uint32_t smw[];
    uint32_t* QtH = smw + OFF_QTH;
    uint32_t* QtL = smw + OFF_QTL;
    uint32_t* KaH = smw + OFF_KAH;
    uint32_t* KaL = smw + OFF_KAL;
    uint32_t* Vs  = smw + OFF_VS;
    uint32_t* Pt  = smw + OFF_PT;
    float* CORR = (float*)(smw + OFF_CORR);
    float* LROW = (float*)(smw + OFF_LROW);

    const int qt = blockIdx.x, bh = blockIdx.y;
    const int b = bh >> 4, h = bh & 15;
    const float* qb = g_q + (size_t)bh * SS * HDD + (size_t)qt * 64 * HDD;
    const float* kb = g_k + (size_t)bh * SS * HDD;
    const float* vb = g_v + (size_t)bh * SS * HDD;

    const int tid = threadIdx.x, wr = tid >> 5, lane = tid & 31;
    const int lr = lane >> 2, lc = lane & 3;
    const int q0w = wr * 16;

#pragma unroll
    for (int i = 0; i < 8; i++) {
        int f4 = tid + i * 128;
        int row = f4 >> 4, c4 = f4 & 15;
        float4 v = *(const float4*)&qb[(size_t)row * HDD + c4 * 4];
        float xv[4] = {v.x, v.y, v.z, v.w};
#pragma unroll
        for (int j = 0; j < 4; j++) {
            uint32_t hi, lo;
            split_tf32(xv[j] * 0.125f, hi, lo);
            QtH[(c4 * 4 + j) * SQ_W + row] = hi;
            QtL[(c4 * 4 + j) * SQ_W + row] = lo;
        }
    }

    float oacc[8][4];
#pragma unroll
    for (int nt = 0; nt < 8; nt++)
#pragma unroll
        for (int i = 0; i < 4; i++) oacc[nt][i] = 0.f;
    float mrow[2][2] = {{-1e30f, -1e30f}, {-1e30f, -1e30f}};
    float lrow[2][2] = {{0.f, 0.f}, {0.f, 0.f}};

    for (int kt = 0; kt <= qt; kt++) {
        __syncthreads();
#pragma unroll
        for (int i = 0; i < 8; i++) {
            int f4 = tid + i * 128;
            int row = f4 >> 4, c4 = f4 & 15;
            float4 kv = *(const float4*)&kb[(size_t)(kt * 64 + row) * HDD + c4 * 4];
            uint4 h4, l4;
            split_tf32(kv.x, h4.x, l4.x); split_tf32(kv.y, h4.y, l4.y);
            split_tf32(kv.z, h4.z, l4.z); split_tf32(kv.w, h4.w, l4.w);
            *(uint4*)&KaH[row * SK_W + c4 * 4] = h4;
            *(uint4*)&KaL[row * SK_W + c4 * 4] = l4;
            float4 vv = *(const float4*)&vb[(size_t)(kt * 64 + row) * HDD + c4 * 4];
            *(uint4*)&Vs[row * SV_W + c4 * 4] =
                make_uint4(f2tf32(vv.x), f2tf32(vv.y), f2tf32(vv.z), f2tf32(vv.w));
        }
        __syncthreads();

        float sacc[4][2][4];
#pragma unroll
        for (int mt = 0; mt < 4; mt++)
#pragma unroll
            for (int nt = 0; nt < 2; nt++)
#pragma unroll
                for (int i = 0; i < 4; i++) sacc[mt][nt][i] = 0.f;

#pragma unroll
        for (int k8 = 0; k8 < 64; k8 += 8) {
            uint32_t bqh[2][2], bql[2][2];
#pragma unroll
            for (int nt = 0; nt < 2; nt++) {
                const int nq = q0w + nt * 8 + lr;
                bqh[nt][0] = QtH[(k8 + lc) * SQ_W + nq];
                bqh[nt][1] = QtH[(k8 + lc + 4) * SQ_W + nq];
                bql[nt][0] = QtL[(k8 + lc) * SQ_W + nq];
                bql[nt][1] = QtL[(k8 + lc + 4) * SQ_W + nq];
            }
#pragma unroll
            for (int mt = 0; mt < 4; mt++) {
                uint32_t ah[4], al[4];
                const int r0 = (mt * 16 + lr) * SK_W, r1 = (mt * 16 + 8 + lr) * SK_W;
                ah[0] = KaH[r0 + k8 + lc];     ah[1] = KaH[r1 + k8 + lc];
                ah[2] = KaH[r0 + k8 + lc + 4]; ah[3] = KaH[r1 + k8 + lc + 4];
                al[0] = KaL[r0 + k8 + lc];     al[1] = KaL[r1 + k8 + lc];
                al[2] = KaL[r0 + k8 + lc + 4]; al[3] = KaL[r1 + k8 + lc + 4];
#pragma unroll
                for (int nt = 0; nt < 2; nt++) {
                    MMA_TF32(sacc[mt][nt], ah, bqh[nt][0], bqh[nt][1]);
                    MMA_TF32(sacc[mt][nt], ah, bql[nt][0], bql[nt][1]);
                    MMA_TF32(sacc[mt][nt], al, bqh[nt][0], bqh[nt][1]);
                }
            }
        }

        if (kt == qt) {
#pragma unroll
            for (int mt = 0; mt < 4; mt++)
#pragma unroll
                for (int nt = 0; nt < 2; nt++)
#pragma unroll
                    for (int c = 0; c < 4; c++) {
                        int kc = mt * 16 + lr + 8 * (c >> 1);
                        int qr = q0w + nt * 8 + 2 * lc + (c & 1);
                        if (kc > qr) sacc[mt][nt][c] = -1e30f;
                    }
        }

#pragma unroll
        for (int nt = 0; nt < 2; nt++) {
#pragma unroll
            for (int par = 0; par < 2; par++) {
                float rm = -1e30f;
#pragma unroll
                for (int mt = 0; mt < 4; mt++) {
                    rm = fmaxf(rm, sacc[mt][nt][par]);
                    rm = fmaxf(rm, sacc[mt][nt][2 + par]);
                }
                rm = fmaxf(rm, __shfl_xor_sync(0xffffffffu, rm, 4));
                rm = fmaxf(rm, __shfl_xor_sync(0xffffffffu, rm, 8));
                rm = fmaxf(rm, __shfl_xor_sync(0xffffffffu, rm, 16));
                float mnew = fmaxf(mrow[nt][par], rm);
                float corr = __expf(mrow[nt][par] - mnew);
                float rs = 0.f;
#pragma unroll
                for (int mt = 0; mt < 4; mt++) {
                    float p0 = __expf(sacc[mt][nt][par] - mnew);
                    float p1 = __expf(sacc[mt][nt][2 + par] - mnew);
                    sacc[mt][nt][par] = p0; sacc[mt][nt][2 + par] = p1;
                    rs += p0 + p1;
                }
                rs += __shfl_xor_sync(0xffffffffu, rs, 4);
                rs += __shfl_xor_sync(0xffffffffu, rs, 8);
                rs += __shfl_xor_sync(0xffffffffu, rs, 16);
                lrow[nt][par] = lrow[nt][par] * corr + rs;
                mrow[nt][par] = mnew;
                if (lr == 0) CORR[q0w + nt * 8 + 2 * lc + par] = corr;
            }
        }

#pragma unroll
        for (int mt = 0; mt < 4; mt++)
#pragma unroll
            for (int nt = 0; nt < 2; nt++)
#pragma unroll
                for (int h2 = 0; h2 < 2; h2++) {
                    int kc = mt * 16 + lr + 8 * h2;
                    int qq = q0w + nt * 8 + 2 * lc;
                    *(uint2*)&Pt[kc * SP_W + qq] = make_uint2(
                        f2tf32(sacc[mt][nt][2 * h2]),
                        f2tf32(sacc[mt][nt][2 * h2 + 1]));
                }
        __syncwarp();

        {
            float cA = CORR[q0w + lr], cB = CORR[q0w + lr + 8];
#pragma unroll
            for (int nt = 0; nt < 8; nt++) {
                oacc[nt][0] *= cA; oacc[nt][1] *= cA;
                oacc[nt][2] *= cB; oacc[nt][3] *= cB;
            }
        }
#pragma unroll
        for (int k8 = 0; k8 < 64; k8 += 8) {
            uint32_t a[4];
            a[0] = Pt[(k8 + lc) * SP_W + q0w + lr];
            a[1] = Pt[(k8 + lc) * SP_W + q0w + 8 + lr];
            a[2] = Pt[(k8 + lc + 4) * SP_W + q0w + lr];
            a[3] = Pt[(k8 + lc + 4) * SP_W + q0w + 8 + lr];
#pragma unroll
            for (int nt = 0; nt < 8; nt++) {
                uint32_t b0 = Vs[(k8 + lc) * SV_W + nt * 8 + lr];
                uint32_t b1 = Vs[(k8 + lc + 4) * SV_W + nt * 8 + lr];
                MMA_TF32(oacc[nt], a, b0, b1);
            }
        }
    }

    if (lr == 0) {
#pragma unroll
        for (int nt = 0; nt < 2; nt++)
#pragma unroll
            for (int par = 0; par < 2; par++)
                LROW[q0w + nt * 8 + 2 * lc + par] = lrow[nt][par];
    }
    __syncwarp();
    {
        float iA = 1.0f / LROW[q0w + lr], iB = 1.0f / LROW[q0w + lr + 8];
        const int qA = qt * 64 + q0w + lr, qB = qA + 8;
        float* dA = g_c + (size_t)(b * SS + qA) * DD + h * 64;
        float* dB = g_c + (size_t)(b * SS + qB) * DD + h * 64;
#pragma unroll
        for (int nt = 0; nt < 8; nt++) {
            const int e = nt * 8 + 2 * lc;
            *(float2*)(dA + e) = make_float2(oacc[nt][0] * iA, oacc[nt][1] * iA);
            *(float2*)(dB + e) = make_float2(oacc[nt][2] * iB, oacc[nt][3] * iB);
        }
    }
}

// ---------------------------------------------------------------------------
// Kernel 3: output projection, tf32 mma.sync, register-staged double buffer.
// CTA 256x64, BK=32, 256 thr / 8 warps, warp 64x32. R7 B-gather per k-half.
// ---------------------------------------------------------------------------
#define OAPAD 36
#define OBPAD 136
#define OA_WORDS (256 * OAPAD)            // 9216
#define OSTAGE   (OA_WORDS + 32 * OBPAD)  // 13568 words = 54272 B

__global__ __launch_bounds__(256) void oproj_mma(
    const float* __restrict__ Wo, float* __restrict__ Y)
{
    extern __shared__ uint32_t so[];      // 2 stages

    const int tid = threadIdx.x;
    const int wid = tid >> 5, lane = tid & 31;
    const int m0w = (wid & 3) * 64, n0w = (wid >> 2) * 32;
    const int m0 = blockIdx.x * 256, n0 = blockIdx.y * 64;
    const int lr = lane >> 2, lc = lane & 3;

    const int brow = tid >> 2, bks = (tid & 3) * 4;   // R7 B-gather mapping

    float acc[4][4][4];
#pragma unroll
    for (int mt = 0; mt < 4; mt++)
#pragma unroll
        for (int nt = 0; nt < 4; nt++)
#pragma unroll
            for (int i = 0; i < 4; i++) acc[mt][nt][i] = 0.f;

    float4 stA[8], stB[2];

    // ---- prologue: tile 0 -> stage 0 ----
#pragma unroll
    for (int i = 0; i < 8; i++) {
        int f4 = tid + i * 256, row = f4 >> 3, c4 = f4 & 7;
        stA[i] = *(const float4*)&g_c[(size_t)(m0 + row) * DD + c4 * 4];
    }
#pragma unroll
    for (int hf = 0; hf < 2; hf++)
        stB[hf] = *(const float4*)&Wo[(size_t)(n0 + brow) * DD + hf * 16 + bks];
#pragma unroll
    for (int i = 0; i < 8; i++) {
        int f4 = tid + i * 256, row = f4 >> 3, c4 = f4 & 7;
        *(uint4*)&so[row * OAPAD + c4 * 4] = cvt4(stA[i]);
    }
#pragma unroll
    for (int hf = 0; hf < 2; hf++) {
        const float fb[4] = {stB[hf].x, stB[hf].y, stB[hf].z, stB[hf].w};
#pragma unroll
        for (int j = 0; j < 4; j++)
            so[OA_WORDS + (hf * 16 + bks + j) * OBPAD + brow] = f2tf32(fb[j]);
    }
    __syncthreads();

    for (int kt = 0; kt < 32; kt++) {
        const int cur = kt & 1;
        uint32_t* As = so + cur * OSTAGE;
        uint32_t* Bs = As + OA_WORDS;
        const bool more = (kt + 1 < 32);

        if (more) {
            const int k1 = (kt + 1) * 32;
#pragma unroll
            for (int i = 0; i < 8; i++) {
                int f4 = tid + i * 256, row = f4 >> 3, c4 = f4 & 7;
                stA[i] = *(const float4*)&g_c[(size_t)(m0 + row) * DD + k1 + c4 * 4];
            }
#pragma unroll
            for (int hf = 0; hf < 2; hf++)
                stB[hf] = *(const float4*)&Wo[(size_t)(n0 + brow) * DD + k1 + hf * 16 + bks];
        }

#pragma unroll
        for (int ks = 0; ks < 4; ks++) {
            const int k8 = ks * 8;
            uint32_t a[4][4];
#pragma unroll
            for (int mt = 0; mt < 4; mt++) {
                const int r = (m0w + mt * 16 + lr) * OAPAD;
                a[mt][0] = As[r + k8 + lc];
                a[mt][1] = As[r + 8 * OAPAD + k8 + lc];
                a[mt][2] = As[r + k8 + lc + 4];
                a[mt][3] = As[r + 8 * OAPAD + k8 + lc + 4];
            }
#pragma unroll
            for (int nt = 0; nt < 4; nt++) {
                const int n = n0w + nt * 8 + lr;
                uint32_t b0 = Bs[(k8 + lc) * OBPAD + n];
                uint32_t b1 = Bs[(k8 + lc + 4) * OBPAD + n];
#pragma unroll
                for (int mt = 0; mt < 4; mt++)
                    MMA_TF32(acc[mt][nt], a[mt], b0, b1);
            }
        }

        if (more) {
            uint32_t* Ad = so + (cur ^ 1) * OSTAGE;
            uint32_t* Bd = Ad + OA_WORDS;
#pragma unroll
            for (int i = 0; i < 8; i++) {
                int f4 = tid + i * 256, row = f4 >> 3, c4 = f4 & 7;
                *(uint4*)&Ad[row * OAPAD + c4 * 4] = cvt4(stA[i]);
            }
#pragma unroll
            for (int hf = 0; hf < 2; hf++) {
                const float fb[4] = {stB[hf].x, stB[hf].y, stB[hf].z, stB[hf].w};
#pragma unroll
                for (int j = 0; j < 4; j++)
                    Bd[(hf * 16 + bks + j) * OBPAD + brow] = f2tf32(fb[j]);
            }
        }
        __syncthreads();
    }

#pragma unroll
    for (int mt = 0; mt < 4; mt++)
#pragma unroll
    for (int half = 0; half < 2; half++) {
        const int m = m0 + m0w + mt * 16 + lr + half * 8;
#pragma unroll
        for (int nt = 0; nt < 4; nt++) {
            const int e = n0w + nt * 8 + 2 * lc;
            *(float2*)&Y[(size_t)m * DD + n0 + e] =
                make_float2(acc[mt][nt][half * 2], acc[mt][nt][half * 2 + 1]);
        }
    }
}

// ---------------------------------------------------------------------------
extern "C" void kernel_launch(void* const* d_in, const int* in_sizes, int n_in,
                              void* d_out, int out_size)
{
    const float* x  = (const float*)d_in[0];
    const float* Wq = (const float*)d_in[1];
    const float* Wk = (const float*)d_in[2];
    const float* Wv = (const float*)d_in[3];
    const float* Wo = (const float*)d_in[4];
    float* y = (float*)d_out;

    const int qkv_smem  = 2 * QSTAGE * 4;   // 92160
    const int oproj_smem = 2 * OSTAGE * 4;  // 108544
    const int attn_smem = ATTN_SMEM_WORDS * 4;  // 109056
    cudaFuncSetAttribute(qkv_mma,
                         cudaFuncAttributeMaxDynamicSharedMemorySize, qkv_smem);
    cudaFuncSetAttribute(oproj_mma,
                         cudaFuncAttributeMaxDynamicSharedMemorySize, oproj_smem);
    cudaFuncSetAttribute(attn_mma,
                         cudaFuncAttributeMaxDynamicSharedMemorySize, attn_smem);

    qkv_mma<<<dim3(MM/256, 48), 256, qkv_smem>>>(x, Wq, Wk, Wv);
    attn_mma<<<dim3(SS/64, BB*HH), 128, attn_smem>>>();
    oproj_mma<<<dim3(MM/256, DD/64), 256, oproj_smem>>>(Wo, y);
}

// round 15
// speedup vs baseline: 1.1572x; 1.1572x over previous
#include <cuda_runtime.h>
#include <cuda_bf16.h>
#include <cstdint>

#define BB 4
#define SS 2048
#define DD 1024
#define HH 16
#define HDD 64
#define MM (BB*SS)   // 8192

// Scratch (allocation-free rule: __device__ globals)
__device__ float g_q[(size_t)BB*HH*SS*HDD];   // [bh][s][e] 32MB
__device__ float g_k[(size_t)BB*HH*SS*HDD];
__device__ float g_v[(size_t)BB*HH*SS*HDD];
__device__ float g_c[(size_t)MM*DD];          // attn out, concat layout [b,s,D]
// tf32-bit pre-converted operands
__device__ uint32_t g_xt[(size_t)MM*DD];            // cvt(x)          32MB
__device__ uint32_t g_wt[(size_t)3*HH*DD*HDD];      // cvt(Wq|Wk|Wv)   12MB
__device__ uint32_t g_wot[(size_t)DD*DD];           // cvt(Wo^T)[k][n]  4MB
__device__ uint32_t g_ct[(size_t)MM*DD];            // cvt(g_c)        32MB

__device__ __forceinline__ uint32_t f2tf32(float f) {
    uint32_t u;
    asm("cvt.rna.tf32.f32 %0, %1;" : "=r"(u) : "f"(f));
    return u;
}

__device__ __forceinline__ uint4 cvt4(float4 v) {
    return make_uint4(f2tf32(v.x), f2tf32(v.y), f2tf32(v.z), f2tf32(v.w));
}

__device__ __forceinline__ void split_tf32(float x, uint32_t& hi, uint32_t& lo) {
    hi = f2tf32(x);
    lo = f2tf32(x - __uint_as_float(hi));
}

__device__ __forceinline__ void cp_async16(uint32_t dst_smem, const void* src) {
    asm volatile("cp.async.cg.shared.global [%0], [%1], 16;"
                 :: "r"(dst_smem), "l"(src));
}
#define CP_COMMIT() asm volatile("cp.async.commit_group;" ::: "memory")
#define CP_WAIT(n)  asm volatile("cp.async.wait_group %0;" :: "n"(n) : "memory")

#define MMA_TF32(c, a, b0, b1) \
    asm volatile("mma.sync.aligned.m16n8k8.row.col.f32.tf32.tf32.f32 " \
        "{%0,%1,%2,%3}, {%4,%5,%6,%7}, {%8,%9}, {%0,%1,%2,%3};" \
        : "+f"((c)[0]), "+f"((c)[1]), "+f"((c)[2]), "+f"((c)[3]) \
        : "r"((a)[0]), "r"((a)[1]), "r"((a)[2]), "r"((a)[3]), "r"(b0), "r"(b1))

// ---------------------------------------------------------------------------
// Convert kernels (one-shot, before/between GEMMs)
// ---------------------------------------------------------------------------
__global__ __launch_bounds__(256) void cvt_kernel(
    const float* __restrict__ src, uint32_t* __restrict__ dst)
{
    int i = blockIdx.x * 256 + threadIdx.x;
    float4 v = ((const float4*)src)[i];
    ((uint4*)dst)[i] = cvt4(v);
}

// dst[k][n] = cvt(Wo[n][k]); 1024x1024, 32x32 tiles via smem transpose
__global__ __launch_bounds__(256) void cvt_wo_t(
    const float* __restrict__ Wo, uint32_t* __restrict__ dst)
{
    __shared__ float tile[32][33];
    const int k0 = blockIdx.x * 32, n0 = blockIdx.y * 32;
    const int tx = threadIdx.x & 31, ty = threadIdx.x >> 5;   // 32 x 8
#pragma unroll
    for (int i = 0; i < 32; i += 8)
        tile[ty + i][tx] = Wo[(size_t)(n0 + ty + i) * DD + k0 + tx];
    __syncthreads();
#pragma unroll
    for (int i = 0; i < 32; i += 8)
        dst[(size_t)(k0 + ty + i) * DD + n0 + tx] = f2tf32(tile[tx][ty + i]);
}

// ---------------------------------------------------------------------------
// Kernel 1: QKV projection, tf32 mma.sync, cp.async 2-stage pipeline.
// CTA 256x64 (one head per n-block), BK=32, 256 thr / 8 warps, warp 64x32.
// Operands pre-converted (g_xt, g_wt) — no cvt in hot loop, no reg staging.
// ---------------------------------------------------------------------------
#define QAPAD 36
#define QBPAD 72
#define QA_WORDS (256 * QAPAD)            // 9216
#define QSTAGE   (QA_WORDS + 32 * QBPAD)  // 11520 words = 46080 B

__global__ __launch_bounds__(256) void qkv_mma(
    const uint32_t* __restrict__ xt, const uint32_t* __restrict__ wt)
{
    extern __shared__ uint32_t sq[];    // 2 stages

    const int tid = threadIdx.x;
    const int wid = tid >> 5, lane = tid & 31;
    const int m0w = (wid & 3) * 64, n0w = (wid >> 2) * 32;
    const int m0 = blockIdx.x * 256;
    const int ct = blockIdx.y;                 // 0..47: which*16 + h
    const int which = ct >> 4, h = ct & 15;
    const uint32_t* Wh = wt + (size_t)ct * DD * HDD;
    float* ob = (which == 0) ? g_q : (which == 1) ? g_k : g_v;

    const int lr = lane >> 2, lc = lane & 3;
    const uint32_t sb = (uint32_t)__cvta_generic_to_shared(sq);

    // loader coords: A piece i -> row (tid>>3)+i*32, col4 tid&7
    //                B piece i -> row (tid>>4)+i*16, col4 tid&15
    const int rA = tid >> 3, cA = tid & 7;
    const int rB = tid >> 4, cB = tid & 15;

    float acc[4][4][4];
#pragma unroll
    for (int mt = 0; mt < 4; mt++)
#pragma unroll
        for (int nt = 0; nt < 4; nt++)
#pragma unroll
            for (int i = 0; i < 4; i++) acc[mt][nt][i] = 0.f;

    // ---- prologue: issue tiles 0 and 1 ----
#pragma unroll
    for (int s = 0; s < 2; s++) {
        const uint32_t dA = sb + (s * QSTAGE) * 4;
        const uint32_t dB = dA + QA_WORDS * 4;
        const int k0 = s * 32;
#pragma unroll
        for (int i = 0; i < 8; i++)
            cp_async16(dA + ((rA + i * 32) * QAPAD + cA * 4) * 4,
                       &xt[(size_t)(m0 + rA + i * 32) * DD + k0 + cA * 4]);
#pragma unroll
        for (int i = 0; i < 2; i++)
            cp_async16(dB + ((rB + i * 16) * QBPAD + cB * 4) * 4,
                       &Wh[(size_t)(k0 + rB + i * 16) * HDD + cB * 4]);
        CP_COMMIT();
    }
    CP_WAIT(1);
    __syncthreads();

    for (int kt = 0; kt < 32; kt++) {
        const int cur = kt & 1;
        uint32_t* As = sq + cur * QSTAGE;
        uint32_t* Bs = As + QA_WORDS;

        // ---- compute current tile ----
#pragma unroll
        for (int ks = 0; ks < 4; ks++) {
            const int k8 = ks * 8;
            uint32_t a[4][4];
#pragma unroll
            for (int mt = 0; mt < 4; mt++) {
                const int r = (m0w + mt * 16 + lr) * QAPAD;
                a[mt][0] = As[r + k8 + lc];
                a[mt][1] = As[r + 8 * QAPAD + k8 + lc];
                a[mt][2] = As[r + k8 + lc + 4];
                a[mt][3] = As[r + 8 * QAPAD + k8 + lc + 4];
            }
#pragma unroll
            for (int nt = 0; nt < 4; nt++) {
                const int n = n0w + nt * 8 + lr;
                uint32_t b0 = Bs[(k8 + lc) * QBPAD + n];
                uint32_t b1 = Bs[(k8 + lc + 4) * QBPAD + n];
#pragma unroll
                for (int mt = 0; mt < 4; mt++)
                    MMA_TF32(acc[mt][nt], a[mt], b0, b1);
            }
        }
        __syncthreads();   // all warps done reading stage cur

        // ---- refill stage cur with tile kt+2; ensure kt+1 landed ----
        if (kt + 2 < 32) {
            const uint32_t dA = sb + (cur * QSTAGE) * 4;
            const uint32_t dB = dA + QA_WORDS * 4;
            const int k0 = (kt + 2) * 32;
#pragma unroll
            for (int i = 0; i < 8; i++)
                cp_async16(dA + ((rA + i * 32) * QAPAD + cA * 4) * 4,
                           &xt[(size_t)(m0 + rA + i * 32) * DD + k0 + cA * 4]);
#pragma unroll
            for (int i = 0; i < 2; i++)
                cp_async16(dB + ((rB + i * 16) * QBPAD + cB * 4) * 4,
                           &Wh[(size_t)(k0 + rB + i * 16) * HDD + cB * 4]);
            CP_COMMIT();
            CP_WAIT(1);
        } else {
            CP_WAIT(0);
        }
        __syncthreads();
    }

    // ---- Epilogue: scatter into [bh][s][e] ----
#pragma unroll
    for (int mt = 0; mt < 4; mt++)
#pragma unroll
    for (int half = 0; half < 2; half++) {
        const int m = m0 + m0w + mt * 16 + lr + half * 8;
        const int b = m >> 11, srow = m & (SS - 1);
        float* dst = ob + ((size_t)(b * HH + h) * SS + srow) * HDD;
#pragma unroll
        for (int nt = 0; nt < 4; nt++) {
            const int e = n0w + nt * 8 + 2 * lc;
            *(float2*)(dst + e) =
                make_float2(acc[mt][nt][half * 2], acc[mt][nt][half * 2 + 1]);
        }
    }
}

// ---------------------------------------------------------------------------
// Kernel 2: flash attention via tf32 mma.sync (byte-identical to R9-R11).
// ---------------------------------------------------------------------------
#define SQ_W 72
#define SK_W 68
#define SV_W 72
#define SP_W 72

#define OFF_QTH 0
#define OFF_QTL 4608
#define OFF_KAH 9216
#define OFF_KAL 13568
#define OFF_VS  17920
#define OFF_PT  22528
#define OFF_CORR 27136
#define OFF_LROW 27200
#define ATTN_SMEM_WORDS 27264   // * 4 = 109056 bytes

__global__ __launch_bounds__(128) void attn_mma() {
    extern __shared__ uint32_t smw[];
    uint32_t* QtH = smw + OFF_QTH;
    uint32_t* QtL = smw + OFF_QTL;
    uint32_t* KaH = smw + OFF_KAH;
    uint32_t* KaL = smw + OFF_KAL;
    uint32_t* Vs  = smw + OFF_VS;
    uint32_t* Pt  = smw + OFF_PT;
    float* CORR = (float*)(smw + OFF_CORR);
    float* LROW = (float*)(smw + OFF_LROW);

    const int qt = blockIdx.x, bh = blockIdx.y;
    const int b = bh >> 4, h = bh & 15;
    const float* qb = g_q + (size_t)bh * SS * HDD + (size_t)qt * 64 * HDD;
    const float* kb = g_k + (size_t)bh * SS * HDD;
    const float* vb = g_v + (size_t)bh * SS * HDD;

    const int tid = threadIdx.x, wr = tid >> 5, lane = tid & 31;
    const int lr = lane >> 2, lc = lane & 3;
    const int q0w = wr * 16;

#pragma unroll
    for (int i = 0; i < 8; i++) {
        int f4 = tid + i * 128;
        int row = f4 >> 4, c4 = f4 & 15;
        float4 v = *(const float4*)&qb[(size_t)row * HDD + c4 * 4];
        float xv[4] = {v.x, v.y, v.z, v.w};
#pragma unroll
        for (int j = 0; j < 4; j++) {
            uint32_t hi, lo;
            split_tf32(xv[j] * 0.125f, hi, lo);
            QtH[(c4 * 4 + j) * SQ_W + row] = hi;
            QtL[(c4 * 4 + j) * SQ_W + row] = lo;
        }
    }

    float oacc[8][4];
#pragma unroll
    for (int nt = 0; nt < 8; nt++)
#pragma unroll
        for (int i = 0; i < 4; i++) oacc[nt][i] = 0.f;
    float mrow[2][2] = {{-1e30f, -1e30f}, {-1e30f, -1e30f}};
    float lrow[2][2] = {{0.f, 0.f}, {0.f, 0.f}};

    for (int kt = 0; kt <= qt; kt++) {
        __syncthreads();
#pragma unroll
        for (int i = 0; i < 8; i++) {
            int f4 = tid + i * 128;
            int row = f4 >> 4, c4 = f4 & 15;
            float4 kv = *(const float4*)&kb[(size_t)(kt * 64 + row) * HDD + c4 * 4];
            uint4 h4, l4;
            split_tf32(kv.x, h4.x, l4.x); split_tf32(kv.y, h4.y, l4.y);
            split_tf32(kv.z, h4.z, l4.z); split_tf32(kv.w, h4.w, l4.w);
            *(uint4*)&KaH[row * SK_W + c4 * 4] = h4;
            *(uint4*)&KaL[row * SK_W + c4 * 4] = l4;
            float4 vv = *(const float4*)&vb[(size_t)(kt * 64 + row) * HDD + c4 * 4];
            *(uint4*)&Vs[row * SV_W + c4 * 4] =
                make_uint4(f2tf32(vv.x), f2tf32(vv.y), f2tf32(vv.z), f2tf32(vv.w));
        }
        __syncthreads();

        float sacc[4][2][4];
#pragma unroll
        for (int mt = 0; mt < 4; mt++)
#pragma unroll
            for (int nt = 0; nt < 2; nt++)
#pragma unroll
                for (int i = 0; i < 4; i++) sacc[mt][nt][i] = 0.f;

#pragma unroll
        for (int k8 = 0; k8 < 64; k8 += 8) {
            uint32_t bqh[2][2], bql[2][2];
#pragma unroll
            for (int nt = 0; nt < 2; nt++) {
                const int nq = q0w + nt * 8 + lr;
                bqh[nt][0] = QtH[(k8 + lc) * SQ_W + nq];
                bqh[nt][1] = QtH[(k8 + lc + 4) * SQ_W + nq];
                bql[nt][0] = QtL[(k8 + lc) * SQ_W + nq];
                bql[nt][1] = QtL[(k8 + lc + 4) * SQ_W + nq];
            }
#pragma unroll
            for (int mt = 0; mt < 4; mt++) {
                uint32_t ah[4], al[4];
                const int r0 = (mt * 16 + lr) * SK_W, r1 = (mt * 16 + 8 + lr) * SK_W;
                ah[0] = KaH[r0 + k8 + lc];     ah[1] = KaH[r1 + k8 + lc];
                ah[2] = KaH[r0 + k8 + lc + 4]; ah[3] = KaH[r1 + k8 + lc + 4];
                al[0] = KaL[r0 + k8 + lc];     al[1] = KaL[r1 + k8 + lc];
                al[2] = KaL[r0 + k8 + lc + 4]; al[3] = KaL[r1 + k8 + lc + 4];
#pragma unroll
                for (int nt = 0; nt < 2; nt++) {
                    MMA_TF32(sacc[mt][nt], ah, bqh[nt][0], bqh[nt][1]);
                    MMA_TF32(sacc[mt][nt], ah, bql[nt][0], bql[nt][1]);
                    MMA_TF32(sacc[mt][nt], al, bqh[nt][0], bqh[nt][1]);
                }
            }
        }

        if (kt == qt) {
#pragma unroll
            for (int mt = 0; mt < 4; mt++)
#pragma unroll
                for (int nt = 0; nt < 2; nt++)
#pragma unroll
                    for (int c = 0; c < 4; c++) {
                        int kc = mt * 16 + lr + 8 * (c >> 1);
                        int qr = q0w + nt * 8 + 2 * lc + (c & 1);
                        if (kc > qr) sacc[mt][nt][c] = -1e30f;
                    }
        }

#pragma unroll
        for (int nt = 0; nt < 2; nt++) {
#pragma unroll
            for (int par = 0; par < 2; par++) {
                float rm = -1e30f;
#pragma unroll
                for (int mt = 0; mt < 4; mt++) {
                    rm = fmaxf(rm, sacc[mt][nt][par]);
                    rm = fmaxf(rm, sacc[mt][nt][2 + par]);
                }
                rm = fmaxf(rm, __shfl_xor_sync(0xffffffffu, rm, 4));
                rm = fmaxf(rm, __shfl_xor_sync(0xffffffffu, rm, 8));
                rm = fmaxf(rm, __shfl_xor_sync(0xffffffffu, rm, 16));
                float mnew = fmaxf(mrow[nt][par], rm);
                float corr = __expf(mrow[nt][par] - mnew);
                float rs = 0.f;
#pragma unroll
                for (int mt = 0; mt < 4; mt++) {
                    float p0 = __expf(sacc[mt][nt][par] - mnew);
                    float p1 = __expf(sacc[mt][nt][2 + par] - mnew);
                    sacc[mt][nt][par] = p0; sacc[mt][nt][2 + par] = p1;
                    rs += p0 + p1;
                }
                rs += __shfl_xor_sync(0xffffffffu, rs, 4);
                rs += __shfl_xor_sync(0xffffffffu, rs, 8);
                rs += __shfl_xor_sync(0xffffffffu, rs, 16);
                lrow[nt][par] = lrow[nt][par] * corr + rs;
                mrow[nt][par] = mnew;
                if (lr == 0) CORR[q0w + nt * 8 + 2 * lc + par] = corr;
            }
        }

#pragma unroll
        for (int mt = 0; mt < 4; mt++)
#pragma unroll
            for (int nt = 0; nt < 2; nt++)
#pragma unroll
                for (int h2 = 0; h2 < 2; h2++) {
                    int kc = mt * 16 + lr + 8 * h2;
                    int qq = q0w + nt * 8 + 2 * lc;
                    *(uint2*)&Pt[kc * SP_W + qq] = make_uint2(
                        f2tf32(sacc[mt][nt][2 * h2]),
                        f2tf32(sacc[mt][nt][2 * h2 + 1]));
                }
        __syncwarp();

        {
            float cA = CORR[q0w + lr], cB = CORR[q0w + lr + 8];
#pragma unroll
            for (int nt = 0; nt < 8; nt++) {
                oacc[nt][0] *= cA; oacc[nt][1] *= cA;
                oacc[nt][2] *= cB; oacc[nt][3] *= cB;
            }
        }
#pragma unroll
        for (int k8 = 0; k8 < 64; k8 += 8) {
            uint32_t a[4];
            a[0] = Pt[(k8 + lc) * SP_W + q0w + lr];
            a[1] = Pt[(k8 + lc) * SP_W + q0w + 8 + lr];
            a[2] = Pt[(k8 + lc + 4) * SP_W + q0w + lr];
            a[3] = Pt[(k8 + lc + 4) * SP_W + q0w + 8 + lr];
#pragma unroll
            for (int nt = 0; nt < 8; nt++) {
                uint32_t b0 = Vs[(k8 + lc) * SV_W + nt * 8 + lr];
                uint32_t b1 = Vs[(k8 + lc + 4) * SV_W + nt * 8 + lr];
                MMA_TF32(oacc[nt], a, b0, b1);
            }
        }
    }

    if (lr == 0) {
#pragma unroll
        for (int nt = 0; nt < 2; nt++)
#pragma unroll
            for (int par = 0; par < 2; par++)
                LROW[q0w + nt * 8 + 2 * lc + par] = lrow[nt][par];
    }
    __syncwarp();
    {
        float iA = 1.0f / LROW[q0w + lr], iB = 1.0f / LROW[q0w + lr + 8];
        const int qA = qt * 64 + q0w + lr, qB = qA + 8;
        float* dA = g_c + (size_t)(b * SS + qA) * DD + h * 64;
        float* dB = g_c + (size_t)(b * SS + qB) * DD + h * 64;
#pragma unroll
        for (int nt = 0; nt < 8; nt++) {
            const int e = nt * 8 + 2 * lc;
            *(float2*)(dA + e) = make_float2(oacc[nt][0] * iA, oacc[nt][1] * iA);
            *(float2*)(dB + e) = make_float2(oacc[nt][2] * iB, oacc[nt][3] * iB);
        }
    }
}

// ---------------------------------------------------------------------------
// Kernel 3: output projection, tf32 mma.sync, cp.async 2-stage pipeline.
// Same geometry as qkv (CTA 256x64, BK=32). A = g_ct, B = g_wot[k][n] direct.
// ---------------------------------------------------------------------------
__global__ __launch_bounds__(256) void oproj_mma(
    const uint32_t* __restrict__ ct, const uint32_t* __restrict__ wot,
    float* __restrict__ Y)
{
    extern __shared__ uint32_t so[];    // 2 stages, QSTAGE layout

    const int tid = threadIdx.x;
    const int wid = tid >> 5, lane = tid & 31;
    const int m0w = (wid & 3) * 64, n0w = (wid >> 2) * 32;
    const int m0 = blockIdx.x * 256, n0 = blockIdx.y * 64;
    const int lr = lane >> 2, lc = lane & 3;
    const uint32_t sb = (uint32_t)__cvta_generic_to_shared(so);

    const int rA = tid >> 3, cA = tid & 7;
    const int rB = tid >> 4, cB = tid & 15;

    float acc[4][4][4];
#pragma unroll
    for (int mt = 0; mt < 4; mt++)
#pragma unroll
        for (int nt = 0; nt < 4; nt++)
#pragma unroll
            for (int i = 0; i < 4; i++) acc[mt][nt][i] = 0.f;

#pragma unroll
    for (int s = 0; s < 2; s++) {
        const uint32_t dA = sb + (s * QSTAGE) * 4;
        const uint32_t dB = dA + QA_WORDS * 4;
        const int k0 = s * 32;
#pragma unroll
        for (int i = 0; i < 8; i++)
            cp_async16(dA + ((rA + i * 32) * QAPAD + cA * 4) * 4,
                       &ct[(size_t)(m0 + rA + i * 32) * DD + k0 + cA * 4]);
#pragma unroll
        for (int i = 0; i < 2; i++)
            cp_async16(dB + ((rB + i * 16) * QBPAD + cB * 4) * 4,
                       &wot[(size_t)(k0 + rB + i * 16) * DD + n0 + cB * 4]);
        CP_COMMIT();
    }
    CP_WAIT(1);
    __syncthreads();

    for (int kt = 0; kt < 32; kt++) {
        const int cur = kt & 1;
        uint32_t* As = so + cur * QSTAGE;
        uint32_t* Bs = As + QA_WORDS;

#pragma unroll
        for (int ks = 0; ks < 4; ks++) {
            const int k8 = ks * 8;
            uint32_t a[4][4];
#pragma unroll
            for (int mt = 0; mt < 4; mt++) {
                const int r = (m0w + mt * 16 + lr) * QAPAD;
                a[mt][0] = As[r + k8 + lc];
                a[mt][1] = As[r + 8 * QAPAD + k8 + lc];
                a[mt][2] = As[r + k8 + lc + 4];
                a[mt][3] = As[r + 8 * QAPAD + k8 + lc + 4];
            }
#pragma unroll
            for (int nt = 0; nt < 4; nt++) {
                const int n = n0w + nt * 8 + lr;
                uint32_t b0 = Bs[(k8 + lc) * QBPAD + n];
                uint32_t b1 = Bs[(k8 + lc + 4) * QBPAD + n];
#pragma unroll
                for (int mt = 0; mt < 4; mt++)
                    MMA_TF32(acc[mt][nt], a[mt], b0, b1);
            }
        }
        __syncthreads();

        if (kt + 2 < 32) {
            const uint32_t dA = sb + (cur * QSTAGE) * 4;
            const uint32_t dB = dA + QA_WORDS * 4;
            const int k0 = (kt + 2) * 32;
#pragma unroll
            for (int i = 0; i < 8; i++)
                cp_async16(dA + ((rA + i * 32) * QAPAD + cA * 4) * 4,
                           &ct[(size_t)(m0 + rA + i * 32) * DD + k0 + cA * 4]);
#pragma unroll
            for (int i = 0; i < 2; i++)
                cp_async16(dB + ((rB + i * 16) * QBPAD + cB * 4) * 4,
                           &wot[(size_t)(k0 + rB + i * 16) * DD + n0 + cB * 4]);
            CP_COMMIT();
            CP_WAIT(1);
        } else {
            CP_WAIT(0);
        }
        __syncthreads();
    }

#pragma unroll
    for (int mt = 0; mt < 4; mt++)
#pragma unroll
    for (int half = 0; half < 2; half++) {
        const int m = m0 + m0w + mt * 16 + lr + half * 8;
#pragma unroll
        for (int nt = 0; nt < 4; nt++) {
            const int e = n0w + nt * 8 + 2 * lc;
            *(float2*)&Y[(size_t)m * DD + n0 + e] =
                make_float2(acc[mt][nt][half * 2], acc[mt][nt][half * 2 + 1]);
        }
    }
}

// ---------------------------------------------------------------------------
extern "C" void kernel_launch(void* const* d_in, const int* in_sizes, int n_in,
                              void* d_out, int out_size)
{
    const float* x  = (const float*)d_in[0];
    const float* Wq = (const float*)d_in[1];
    const float* Wk = (const float*)d_in[2];
    const float* Wv = (const float*)d_in[3];
    const float* Wo = (const float*)d_in[4];
    float* y = (float*)d_out;

    const int mm_smem  = 2 * QSTAGE * 4;        // 92160
    const int attn_smem = ATTN_SMEM_WORDS * 4;  // 109056
    cudaFuncSetAttribute(qkv_mma,
                         cudaFuncAttributeMaxDynamicSharedMemorySize, mm_smem);
    cudaFuncSetAttribute(oproj_mma,
                         cudaFuncAttributeMaxDynamicSharedMemorySize, mm_smem);
    cudaFuncSetAttribute(attn_mma,
                         cudaFuncAttributeMaxDynamicSharedMemorySize, attn_smem);

    // device-global scratch addresses (host-side)
    uint32_t *p_xt, *p_wt, *p_wot, *p_ct;
    float* p_gc;
    cudaGetSymbolAddress((void**)&p_xt,  g_xt);
    cudaGetSymbolAddress((void**)&p_wt,  g_wt);
    cudaGetSymbolAddress((void**)&p_wot, g_wot);
    cudaGetSymbolAddress((void**)&p_ct,  g_ct);
    cudaGetSymbolAddress((void**)&p_gc,  g_c);

    const int WSZ = HH * DD * HDD;   // 1048576 elems per weight tensor

    // pre-convert operands to tf32 bits
    cvt_kernel<<<MM*DD/1024, 256>>>(x, p_xt);
    cvt_kernel<<<WSZ/1024, 256>>>(Wq, p_wt);
    cvt_kernel<<<WSZ/1024, 256>>>(Wk, p_wt + WSZ);
    cvt_kernel<<<WSZ/1024, 256>>>(Wv, p_wt + 2*WSZ);
    cvt_wo_t<<<dim3(32, 32), 256>>>(Wo, p_wot);

    qkv_mma<<<dim3(MM/256, 48), 256, mm_smem>>>(p_xt, p_wt);
    attn_mma<<<dim3(SS/64, BB*HH), 128, attn_smem>>>();
    cvt_kernel<<<MM*DD/1024, 256>>>(p_gc, p_ct);
    oproj_mma<<<dim3(MM/256, DD/64), 256, mm_smem>>>(p_ct, p_wot, y);
}